// round 3
// baseline (speedup 1.0000x reference)
#include <cuda_runtime.h>

// focal_loss: out = COEF * sum_i ( idx==0 ? log(p) : idx==1 ? log(1-p) : 0 )
// COEF = 0.1 * (1-0.8)^2 = 0.004
// Single fused kernel, persistent one-wave grid (148 SMs x 8 blocks),
// simple float4 grid-stride streaming (R1-proven 6.2 TB/s), threadfence
// last-block final fold. Deterministic; no allocations; graph-replay safe.

#define NBLOCKS  1184   // 148 SMs * 8 blocks -> exactly one wave
#define NTHREADS 256

__device__ float        g_partials[NBLOCKS];
__device__ unsigned int g_count = 0;

__device__ __forceinline__ float term_of(float p, int idx) {
    // idx==0 -> log(p); idx==1 -> log(1-p); else log(1)=0. One MUFU per elem.
    float x = (idx == 0) ? p : ((idx == 1) ? (1.0f - p) : 1.0f);
    return __logf(x);
}

__device__ __forceinline__ float block_reduce(float acc) {
    #pragma unroll
    for (int o = 16; o > 0; o >>= 1)
        acc += __shfl_down_sync(0xffffffffu, acc, o);
    __shared__ float s[NTHREADS / 32];
    if ((threadIdx.x & 31) == 0) s[threadIdx.x >> 5] = acc;
    __syncthreads();
    float v = 0.0f;
    if (threadIdx.x < 32) {
        v = (threadIdx.x < NTHREADS / 32) ? s[threadIdx.x] : 0.0f;
        #pragma unroll
        for (int o = 4; o > 0; o >>= 1)
            v += __shfl_down_sync(0xffffffffu, v, o);
    }
    return v;   // valid in thread 0
}

__global__ void __launch_bounds__(NTHREADS, 8)
focal_loss_fused(const float* __restrict__ p, const int* __restrict__ idx,
                 int n, int n4, float* __restrict__ out) {
    const float4* __restrict__ p4 = reinterpret_cast<const float4*>(p);
    const int4*   __restrict__ i4 = reinterpret_cast<const int4*>(idx);

    const int stride = NBLOCKS * NTHREADS;
    float acc = 0.0f;

    // Simple grid-stride: occupancy (64 warps/SM) supplies the MLP.
    for (int i = blockIdx.x * NTHREADS + threadIdx.x; i < n4; i += stride) {
        float4 a = p4[i];
        int4   b = i4[i];
        acc += term_of(a.x, b.x) + term_of(a.y, b.y)
             + term_of(a.z, b.z) + term_of(a.w, b.w);
    }

    float bsum = block_reduce(acc);
    __shared__ bool s_last;
    if (threadIdx.x == 0) {
        g_partials[blockIdx.x] = bsum;
        __threadfence();
        unsigned int done = atomicAdd(&g_count, 1u);
        s_last = (done == (unsigned int)(gridDim.x - 1));
    }
    __syncthreads();

    if (s_last) {
        // Last block: fold all partials (visible via threadfence+atomic chain)
        float f = 0.0f;
        for (int k = threadIdx.x; k < NBLOCKS; k += NTHREADS)
            f += g_partials[k];
        // scalar tail (n not multiple of 4) — empty for N=16M, kept for safety
        for (int k = n4 * 4 + (int)threadIdx.x; k < n; k += NTHREADS)
            f += term_of(p[k], idx[k]);

        __syncthreads();   // shared s[] reuse inside block_reduce
        float total = block_reduce(f);
        if (threadIdx.x == 0) {
            out[0] = 0.004f * total;   // COEF
            g_count = 0;               // reset for next graph replay
        }
    }
}

extern "C" void kernel_launch(void* const* d_in, const int* in_sizes, int n_in,
                              void* d_out, int out_size) {
    const float* p   = (const float*)d_in[0];
    const int*   idx = (const int*)d_in[1];
    float* out = (float*)d_out;
    int n  = in_sizes[0];
    int n4 = n >> 2;

    focal_loss_fused<<<NBLOCKS, NTHREADS>>>(p, idx, n, n4, out);
}

// round 4
// speedup vs baseline: 1.0760x; 1.0760x over previous
#include <cuda_runtime.h>

// focal_loss: out = COEF * sum_i ( idx==0 ? log(p) : idx==1 ? log(1-p) : 0 )
// COEF = 0.1 * (1-0.8)^2 = 0.004
// Single fused kernel, persistent one-wave grid (148 SMs x 8 blocks),
// float4 grid-stride streaming with __ldcs (evict-first: read-once 128MiB
// stream must not churn L2), threadfence last-block final fold.
// Deterministic; no allocations; graph-replay safe.

#define NBLOCKS  1184u   // 148 SMs * 8 blocks -> exactly one wave
#define NTHREADS 256u

__device__ float        g_partials[NBLOCKS];
__device__ unsigned int g_count = 0;

__device__ __forceinline__ float term_of(float p, int idx) {
    // idx==0 -> log(p); idx==1 -> log(1-p); else log(1)=0. One MUFU per elem.
    float x = (idx == 0) ? p : ((idx == 1) ? (1.0f - p) : 1.0f);
    return __logf(x);
}

__device__ __forceinline__ float block_reduce(float acc) {
    #pragma unroll
    for (int o = 16; o > 0; o >>= 1)
        acc += __shfl_down_sync(0xffffffffu, acc, o);
    __shared__ float s[NTHREADS / 32];
    if ((threadIdx.x & 31) == 0) s[threadIdx.x >> 5] = acc;
    __syncthreads();
    float v = 0.0f;
    if (threadIdx.x < 32) {
        v = (threadIdx.x < NTHREADS / 32) ? s[threadIdx.x] : 0.0f;
        #pragma unroll
        for (int o = 4; o > 0; o >>= 1)
            v += __shfl_down_sync(0xffffffffu, v, o);
    }
    return v;   // valid in thread 0
}

__global__ void __launch_bounds__(NTHREADS, 8)
focal_loss_fused(const float* __restrict__ p, const int* __restrict__ idx,
                 unsigned int n, unsigned int n4, float* __restrict__ out) {
    const float4* __restrict__ p4 = reinterpret_cast<const float4*>(p);
    const int4*   __restrict__ i4 = reinterpret_cast<const int4*>(idx);

    const unsigned int stride = NBLOCKS * NTHREADS;
    float acc = 0.0f;

    // Streaming loads (evict-first): data is read exactly once, keep it out
    // of L2's retention path. Occupancy (64 warps/SM) supplies the MLP.
    for (unsigned int i = blockIdx.x * NTHREADS + threadIdx.x; i < n4; i += stride) {
        float4 a = __ldcs(&p4[i]);
        int4   b = __ldcs(&i4[i]);
        acc += term_of(a.x, b.x) + term_of(a.y, b.y)
             + term_of(a.z, b.z) + term_of(a.w, b.w);
    }

    float bsum = block_reduce(acc);
    __shared__ bool s_last;
    if (threadIdx.x == 0) {
        g_partials[blockIdx.x] = bsum;
        __threadfence();
        unsigned int done = atomicAdd(&g_count, 1u);
        s_last = (done == (unsigned int)(gridDim.x - 1));
    }
    __syncthreads();

    if (s_last) {
        // Last block: fold all partials (visible via threadfence+atomic chain)
        float f = 0.0f;
        for (unsigned int k = threadIdx.x; k < NBLOCKS; k += NTHREADS)
            f += g_partials[k];
        // scalar tail (n not multiple of 4) — empty for N=16M, kept for safety
        for (unsigned int k = n4 * 4u + threadIdx.x; k < n; k += NTHREADS)
            f += term_of(p[k], idx[k]);

        __syncthreads();   // shared s[] reuse inside block_reduce
        float total = block_reduce(f);
        if (threadIdx.x == 0) {
            out[0] = 0.004f * total;   // COEF
            g_count = 0;               // reset for next graph replay
        }
    }
}

extern "C" void kernel_launch(void* const* d_in, const int* in_sizes, int n_in,
                              void* d_out, int out_size) {
    const float* p   = (const float*)d_in[0];
    const int*   idx = (const int*)d_in[1];
    float* out = (float*)d_out;
    unsigned int n  = (unsigned int)in_sizes[0];
    unsigned int n4 = n >> 2;

    focal_loss_fused<<<NBLOCKS, NTHREADS>>>(p, idx, n, n4, out);
}